// round 4
// baseline (speedup 1.0000x reference)
#include <cuda_runtime.h>

// Fixed shapes: B=8, H=8, S=16384, Dv=64, d_k=1
#define BH      64
#define SEQ     16384
#define DV      64
#define NSPLIT  16
#define CHUNK   (SEQ / NSPLIT)   // 1024 rows per split
#define PSTRIDE 68               // 64 ktv + ksq + qsq, padded to float4 stride
#define NGROUP  4
#define BH_PER_GROUP (BH / NGROUP)   // 16 bh per pipeline chunk

__device__ float g_part[BH * NSPLIT * PSTRIDE];

// Static stream + events, created at load time (NOT during capture, no device
// memory). Reused every call; during graph capture they become graph edges.
static cudaStream_t g_s1;
static cudaEvent_t  g_evR[NGROUP];
static cudaEvent_t  g_evJoin;
namespace {
struct InitStreams {
    InitStreams() {
        cudaStreamCreateWithFlags(&g_s1, cudaStreamNonBlocking);
        for (int i = 0; i < NGROUP; ++i)
            cudaEventCreateWithFlags(&g_evR[i], cudaEventDisableTiming);
        cudaEventCreateWithFlags(&g_evJoin, cudaEventDisableTiming);
    }
};
InitStreams g_init_streams;
}

// ---------------------------------------------------------------------------
// Kernel 1: per-(bh, split) partial reduction for one bh-group.
// ---------------------------------------------------------------------------
__global__ __launch_bounds__(256) void reduce_kernel(
    const float* __restrict__ Q,
    const float* __restrict__ K,
    const float* __restrict__ V,
    int bh0)
{
    const int bh    = bh0 + blockIdx.x / NSPLIT;
    const int split = blockIdx.x % NSPLIT;
    const int t     = threadIdx.x;
    const int colg  = t & 15;
    const int rowg  = t >> 4;

    const float4* __restrict__ Vp4 =
        reinterpret_cast<const float4*>(V + (size_t)bh * SEQ * DV + (size_t)(split * CHUNK) * DV);
    const float4* __restrict__ Kp4 =
        reinterpret_cast<const float4*>(K + bh * SEQ + split * CHUNK);
    const float4* __restrict__ Qp4 =
        reinterpret_cast<const float4*>(Q + bh * SEQ + split * CHUNK);

    __shared__ float sK[CHUNK];

    float4 kv = Kp4[t];
    reinterpret_cast<float4*>(sK)[t] = kv;
    float ksq = kv.x * kv.x + kv.y * kv.y + kv.z * kv.z + kv.w * kv.w;
    float4 qv = Qp4[t];
    float qsq = qv.x * qv.x + qv.y * qv.y + qv.z * qv.z + qv.w * qv.w;
    __syncthreads();

    float4 a0 = make_float4(0.f, 0.f, 0.f, 0.f);
    float4 a1 = make_float4(0.f, 0.f, 0.f, 0.f);

    #pragma unroll 4
    for (int r = rowg; r < CHUNK; r += 32) {
        float  k0 = sK[r];
        float4 v0 = __ldcs(&Vp4[(size_t)r * 16 + colg]);
        float  k1 = sK[r + 16];
        float4 v1 = __ldcs(&Vp4[(size_t)(r + 16) * 16 + colg]);
        a0.x += k0 * v0.x;  a0.y += k0 * v0.y;  a0.z += k0 * v0.z;  a0.w += k0 * v0.w;
        a1.x += k1 * v1.x;  a1.y += k1 * v1.y;  a1.z += k1 * v1.z;  a1.w += k1 * v1.w;
    }
    a0.x += a1.x; a0.y += a1.y; a0.z += a1.z; a0.w += a1.w;

    a0.x += __shfl_xor_sync(0xFFFFFFFFu, a0.x, 16);
    a0.y += __shfl_xor_sync(0xFFFFFFFFu, a0.y, 16);
    a0.z += __shfl_xor_sync(0xFFFFFFFFu, a0.z, 16);
    a0.w += __shfl_xor_sync(0xFFFFFFFFu, a0.w, 16);

    #pragma unroll
    for (int m = 16; m >= 1; m >>= 1) {
        ksq += __shfl_xor_sync(0xFFFFFFFFu, ksq, m);
        qsq += __shfl_xor_sync(0xFFFFFFFFu, qsq, m);
    }

    __shared__ float4 s_acc[8][16];
    __shared__ float  s_ksq[8];
    __shared__ float  s_qsq[8];
    const int warp = t >> 5;
    const int lane = t & 31;
    if (lane < 16) s_acc[warp][lane] = a0;
    if (lane == 0) { s_ksq[warp] = ksq; s_qsq[warp] = qsq; }
    __syncthreads();

    float* __restrict__ outp = g_part + (size_t)(bh * NSPLIT + split) * PSTRIDE;
    if (t < 16) {
        float4 a = s_acc[0][t];
        #pragma unroll
        for (int w = 1; w < 8; ++w) {
            float4 b = s_acc[w][t];
            a.x += b.x; a.y += b.y; a.z += b.z; a.w += b.w;
        }
        reinterpret_cast<float4*>(outp)[t] = a;
    } else if (t == 16) {
        float a = 0.f, b = 0.f;
        #pragma unroll
        for (int w = 0; w < 8; ++w) { a += s_ksq[w]; b += s_qsq[w]; }
        outp[64] = a;
        outp[65] = b;
    }
}

// ---------------------------------------------------------------------------
// Kernel 2: fused combine + broadcast for one bh-group.
// ---------------------------------------------------------------------------
#define BROWS 256
__global__ __launch_bounds__(256) void broadcast_kernel(
    const float* __restrict__ Q,
    float* __restrict__ out,
    int bh0)
{
    const size_t row0 = (size_t)bh0 * SEQ + (size_t)blockIdx.x * BROWS;
    const int    t    = threadIdx.x;
    const int    bh   = (int)(row0 >> 14);

    __shared__ float s_coef[DV];
    __shared__ float s_scale;
    __shared__ float sQ[BROWS];

    sQ[t] = Q[row0 + t];

    const float* __restrict__ base = g_part + (size_t)bh * NSPLIT * PSTRIDE;
    if (t < DV) {
        float ktv = 0.f;
        #pragma unroll
        for (int s = 0; s < NSPLIT; ++s) ktv += base[(size_t)s * PSTRIDE + t];
        s_coef[t] = ktv;
    } else if (t == DV) {
        float ksq = 0.f, qsq = 0.f;
        #pragma unroll
        for (int s = 0; s < NSPLIT; ++s) {
            ksq += base[(size_t)s * PSTRIDE + 64];
            qsq += base[(size_t)s * PSTRIDE + 65];
        }
        s_scale = 1.0f / (sqrtf(ksq) * sqrtf(qsq));
    }
    __syncthreads();

    const int rg = t >> 4;
    const int cg = t & 15;
    const float scale = s_scale;
    float4 c = reinterpret_cast<const float4*>(s_coef)[cg];
    c.x *= scale; c.y *= scale; c.z *= scale; c.w *= scale;

    #pragma unroll
    for (int ri = 0; ri < BROWS / 16; ++ri) {
        const int    lr  = ri * 16 + rg;
        const size_t row = row0 + lr;
        const float  q   = sQ[lr];
        float4 o;
        o.x = q * c.x;
        o.y = q * c.y;
        o.z = q * c.z;
        o.w = q * c.w;
        __stcs(reinterpret_cast<float4*>(out) + row * 16 + cg, o);
    }
}

// ---------------------------------------------------------------------------
// Pipelined launch: stream 0 runs the 4 reduce chunks back-to-back (continuous
// read stream); stream 1 runs each broadcast chunk as soon as its reduce chunk
// completes, overlapping the write stream of group i with the reads of i+1.
// ---------------------------------------------------------------------------
extern "C" void kernel_launch(void* const* d_in, const int* in_sizes, int n_in,
                              void* d_out, int out_size)
{
    const float* Q = (const float*)d_in[0];
    const float* K = (const float*)d_in[1];
    const float* V = (const float*)d_in[2];
    float* out = (float*)d_out;

    for (int g = 0; g < NGROUP; ++g) {
        const int bh0 = g * BH_PER_GROUP;
        reduce_kernel<<<BH_PER_GROUP * NSPLIT, 256>>>(Q, K, V, bh0);
        cudaEventRecord(g_evR[g], 0);
        cudaStreamWaitEvent(g_s1, g_evR[g], 0);
        broadcast_kernel<<<(BH_PER_GROUP * SEQ) / BROWS, 256, 0, g_s1>>>(Q, out, bh0);
    }
    // Join the side stream back into the capture/launch stream.
    cudaEventRecord(g_evJoin, g_s1);
    cudaStreamWaitEvent(0, g_evJoin, 0);
}

// round 5
// speedup vs baseline: 1.3416x; 1.3416x over previous
#include <cuda_runtime.h>

// Fixed shapes: B=8, H=8, S=16384, Dv=64, d_k=1
#define BH      64
#define SEQ     16384
#define DV      64
#define NSPLIT  16
#define CHUNK   (SEQ / NSPLIT)   // 1024 rows per reduce item
#define PSTRIDE 68               // 64 ktv + ksq + qsq, float4-aligned stride
#define NCTA    512
#define BROWS   256              // rows per broadcast chunk
#define BCHUNKS 8                // broadcast chunks per CTA (8*256 = 2048 rows)

__device__ float g_part[BH * NSPLIT * PSTRIDE];
__device__ int   g_done[BH];   // reduce-splits completed per bh (0..16), self-resetting
__device__ int   g_bfin[BH];   // broadcast CTAs completed per bh (0..8), self-resetting

struct Smem {
    float  sK[CHUNK];          // reduce: K chunk; broadcast: first 256 = Q slice
    float4 s_acc[8][16];
    float  s_ksq[8];
    float  s_qsq[8];
    float  s_coef[DV];
    float  s_scale;
};

// ---------------------------------------------------------------------------
// Reduce one (bh, split) item: partial K^T V + ||K||^2, ||Q||^2 -> g_part,
// then release-signal g_done[bh].
// ---------------------------------------------------------------------------
__device__ __forceinline__ void do_reduce(
    const float* __restrict__ Q, const float* __restrict__ K,
    const float* __restrict__ V, int bh, int split, Smem& sm, int t)
{
    const int colg = t & 15;
    const int rowg = t >> 4;

    const float4* __restrict__ Vp4 =
        reinterpret_cast<const float4*>(V + (size_t)bh * SEQ * DV + (size_t)(split * CHUNK) * DV);
    const float4* __restrict__ Kp4 =
        reinterpret_cast<const float4*>(K + bh * SEQ + split * CHUNK);
    const float4* __restrict__ Qp4 =
        reinterpret_cast<const float4*>(Q + bh * SEQ + split * CHUNK);

    float4 kv = Kp4[t];
    reinterpret_cast<float4*>(sm.sK)[t] = kv;
    float ksq = kv.x * kv.x + kv.y * kv.y + kv.z * kv.z + kv.w * kv.w;
    float4 qv = Qp4[t];
    float qsq = qv.x * qv.x + qv.y * qv.y + qv.z * qv.z + qv.w * qv.w;
    __syncthreads();

    float4 a0 = make_float4(0.f, 0.f, 0.f, 0.f);
    float4 a1 = make_float4(0.f, 0.f, 0.f, 0.f);

    #pragma unroll 4
    for (int r = rowg; r < CHUNK; r += 32) {
        float  k0 = sm.sK[r];
        float4 v0 = __ldcs(&Vp4[(size_t)r * 16 + colg]);
        float  k1 = sm.sK[r + 16];
        float4 v1 = __ldcs(&Vp4[(size_t)(r + 16) * 16 + colg]);
        a0.x += k0 * v0.x;  a0.y += k0 * v0.y;  a0.z += k0 * v0.z;  a0.w += k0 * v0.w;
        a1.x += k1 * v1.x;  a1.y += k1 * v1.y;  a1.z += k1 * v1.z;  a1.w += k1 * v1.w;
    }
    a0.x += a1.x; a0.y += a1.y; a0.z += a1.z; a0.w += a1.w;

    a0.x += __shfl_xor_sync(0xFFFFFFFFu, a0.x, 16);
    a0.y += __shfl_xor_sync(0xFFFFFFFFu, a0.y, 16);
    a0.z += __shfl_xor_sync(0xFFFFFFFFu, a0.z, 16);
    a0.w += __shfl_xor_sync(0xFFFFFFFFu, a0.w, 16);

    #pragma unroll
    for (int m = 16; m >= 1; m >>= 1) {
        ksq += __shfl_xor_sync(0xFFFFFFFFu, ksq, m);
        qsq += __shfl_xor_sync(0xFFFFFFFFu, qsq, m);
    }

    const int warp = t >> 5;
    const int lane = t & 31;
    if (lane < 16) sm.s_acc[warp][lane] = a0;
    if (lane == 0) { sm.s_ksq[warp] = ksq; sm.s_qsq[warp] = qsq; }
    __syncthreads();

    float* __restrict__ outp = g_part + (size_t)(bh * NSPLIT + split) * PSTRIDE;
    if (t < 16) {
        float4 a = sm.s_acc[0][t];
        #pragma unroll
        for (int w = 1; w < 8; ++w) {
            float4 b = sm.s_acc[w][t];
            a.x += b.x; a.y += b.y; a.z += b.z; a.w += b.w;
        }
        reinterpret_cast<float4*>(outp)[t] = a;
    } else if (t == 16) {
        float a = 0.f, b = 0.f;
        #pragma unroll
        for (int w = 0; w < 8; ++w) { a += sm.s_ksq[w]; b += sm.s_qsq[w]; }
        outp[64] = a;
        outp[65] = b;
    }

    // Release: make g_part writes device-visible, then count this split done.
    __threadfence();
    __syncthreads();
    if (t == 0) atomicAdd(&g_done[bh], 1);
}

// ---------------------------------------------------------------------------
// Broadcast 2048 rows of one bh: wait for all 16 splits, combine coef once,
// then 8 chunks of pure streaming float4 stores. Last finisher resets flags.
// ---------------------------------------------------------------------------
__device__ __forceinline__ void do_broadcast(
    const float* __restrict__ Q, float* __restrict__ out,
    int bh, int part, Smem& sm, int t)   // part in [0,8): which 2048-row slice
{
    // Acquire: wait for all reduce splits of this bh.
    if (t == 0) {
        while (((volatile int*)g_done)[bh] < NSPLIT) __nanosleep(64);
        __threadfence();
    }
    __syncthreads();

    // Combine partials -> coef (same summation order as before: deterministic).
    const float* __restrict__ base = g_part + (size_t)bh * NSPLIT * PSTRIDE;
    if (t < DV) {
        float ktv = 0.f;
        #pragma unroll
        for (int s = 0; s < NSPLIT; ++s) ktv += base[(size_t)s * PSTRIDE + t];
        sm.s_coef[t] = ktv;
    } else if (t == DV) {
        float ksq = 0.f, qsq = 0.f;
        #pragma unroll
        for (int s = 0; s < NSPLIT; ++s) {
            ksq += base[(size_t)s * PSTRIDE + 64];
            qsq += base[(size_t)s * PSTRIDE + 65];
        }
        sm.s_scale = 1.0f / (sqrtf(ksq) * sqrtf(qsq));
    }
    __syncthreads();

    const int rg = t >> 4;
    const int cg = t & 15;
    const float scale = sm.s_scale;
    float4 c4 = reinterpret_cast<const float4*>(sm.s_coef)[cg];
    c4.x *= scale; c4.y *= scale; c4.z *= scale; c4.w *= scale;
    __syncthreads();   // coef consumed into regs before sK reuse below

    const size_t base_row = (size_t)bh * SEQ + (size_t)part * (BCHUNKS * BROWS);

    #pragma unroll 1
    for (int ch = 0; ch < BCHUNKS; ++ch) {
        const size_t row0 = base_row + (size_t)ch * BROWS;
        sm.sK[t] = Q[row0 + t];          // stage 256 Q values (coalesced)
        __syncthreads();
        #pragma unroll
        for (int ri = 0; ri < BROWS / 16; ++ri) {
            const int    lr  = ri * 16 + rg;
            const size_t row = row0 + lr;
            const float  q   = sm.sK[lr];
            float4 o;
            o.x = q * c4.x;
            o.y = q * c4.y;
            o.z = q * c4.z;
            o.w = q * c4.w;
            __stcs(reinterpret_cast<float4*>(out) + row * 16 + cg, o);
        }
        __syncthreads();
    }

    // Self-cleaning counters for graph replay.
    if (t == 0) {
        int v = atomicAdd(&g_bfin[bh], 1);
        if (v == BCHUNKS - 1) {   // 8th CTA of this bh
            g_done[bh] = 0;
            g_bfin[bh] = 0;
        }
    }
}

// ---------------------------------------------------------------------------
// Persistent fused kernel, 512 CTAs (all resident: occ limit >= 8 CTA/SM).
// Skewed schedule mixes read-phase and write-phase across CTA halves.
// ---------------------------------------------------------------------------
__global__ __launch_bounds__(256, 4) void fused_kernel(
    const float* __restrict__ Q,
    const float* __restrict__ K,
    const float* __restrict__ V,
    float* __restrict__ out)
{
    const int c = blockIdx.x;
    const int t = threadIdx.x;
    __shared__ Smem sm;

    const int bh_r0 = c / 16;           // first reduce item: bh in [0,32)
    const int bh_r1 = 32 + c / 16;      // second reduce item: bh in [32,64)
    const int split = c & 15;
    const int bh_b  = c / 8;            // broadcast bh: [0,32) for c<256, [32,64) else
    const int part  = c & 7;

    if (c < 256) {
        do_reduce(Q, K, V, bh_r0, split, sm, t);
        do_broadcast(Q, out, bh_b, part, sm, t);     // bh_b < 32: round-1 producers
        do_reduce(Q, K, V, bh_r1, split, sm, t);
    } else {
        do_reduce(Q, K, V, bh_r0, split, sm, t);
        do_reduce(Q, K, V, bh_r1, split, sm, t);
        do_broadcast(Q, out, bh_b, part, sm, t);     // bh_b >= 32: round-2 producers
    }
}

// ---------------------------------------------------------------------------
extern "C" void kernel_launch(void* const* d_in, const int* in_sizes, int n_in,
                              void* d_out, int out_size)
{
    const float* Q = (const float*)d_in[0];
    const float* K = (const float*)d_in[1];
    const float* V = (const float*)d_in[2];
    float* out = (float*)d_out;

    fused_kernel<<<NCTA, 256>>>(Q, K, V, out);
}

// round 6
// speedup vs baseline: 1.3572x; 1.0116x over previous
#include <cuda_runtime.h>

// Fixed shapes: B=8, H=8, S=16384, Dv=64, d_k=1
#define BH      64
#define SEQ     16384
#define DV      64
#define NSPLIT  16
#define CHUNK   (SEQ / NSPLIT)   // 1024 rows per split
#define PSTRIDE 68               // 64 ktv + ksq + qsq, padded to float4 stride

__device__ float g_part[BH * NSPLIT * PSTRIDE];

// ---------------------------------------------------------------------------
// Kernel 1: per-(bh, split) partial reduction.
//   4 independent __ldcs float4 loads per body (stride-64 rows), 4 accums.
// ---------------------------------------------------------------------------
__global__ __launch_bounds__(256) void reduce_kernel(
    const float* __restrict__ Q,
    const float* __restrict__ K,
    const float* __restrict__ V)
{
    const int bh    = blockIdx.x / NSPLIT;
    const int split = blockIdx.x % NSPLIT;
    const int t     = threadIdx.x;
    const int colg  = t & 15;
    const int rowg  = t >> 4;

    const float4* __restrict__ Vp4 =
        reinterpret_cast<const float4*>(V + (size_t)bh * SEQ * DV + (size_t)(split * CHUNK) * DV);
    const float4* __restrict__ Kp4 =
        reinterpret_cast<const float4*>(K + bh * SEQ + split * CHUNK);
    const float4* __restrict__ Qp4 =
        reinterpret_cast<const float4*>(Q + bh * SEQ + split * CHUNK);

    __shared__ float sK[CHUNK];

    float4 kv = Kp4[t];
    reinterpret_cast<float4*>(sK)[t] = kv;
    float ksq = kv.x * kv.x + kv.y * kv.y + kv.z * kv.z + kv.w * kv.w;
    float4 qv = Qp4[t];
    float qsq = qv.x * qv.x + qv.y * qv.y + qv.z * qv.z + qv.w * qv.w;
    __syncthreads();

    float4 a0 = make_float4(0.f, 0.f, 0.f, 0.f);
    float4 a1 = make_float4(0.f, 0.f, 0.f, 0.f);
    float4 a2 = make_float4(0.f, 0.f, 0.f, 0.f);
    float4 a3 = make_float4(0.f, 0.f, 0.f, 0.f);

    // 16 bodies of 4 independent loads; unroll 2 -> 8 loads in flight.
    #pragma unroll 2
    for (int r = rowg; r < CHUNK; r += 64) {
        float4 v0 = __ldcs(&Vp4[(size_t)(r      ) * 16 + colg]);
        float4 v1 = __ldcs(&Vp4[(size_t)(r + 16) * 16 + colg]);
        float4 v2 = __ldcs(&Vp4[(size_t)(r + 32) * 16 + colg]);
        float4 v3 = __ldcs(&Vp4[(size_t)(r + 48) * 16 + colg]);
        float k0 = sK[r];
        float k1 = sK[r + 16];
        float k2 = sK[r + 32];
        float k3 = sK[r + 48];
        a0.x += k0 * v0.x;  a0.y += k0 * v0.y;  a0.z += k0 * v0.z;  a0.w += k0 * v0.w;
        a1.x += k1 * v1.x;  a1.y += k1 * v1.y;  a1.z += k1 * v1.z;  a1.w += k1 * v1.w;
        a2.x += k2 * v2.x;  a2.y += k2 * v2.y;  a2.z += k2 * v2.z;  a2.w += k2 * v2.w;
        a3.x += k3 * v3.x;  a3.y += k3 * v3.y;  a3.z += k3 * v3.z;  a3.w += k3 * v3.w;
    }
    a0.x += a2.x; a0.y += a2.y; a0.z += a2.z; a0.w += a2.w;
    a1.x += a3.x; a1.y += a3.y; a1.z += a3.z; a1.w += a3.w;
    a0.x += a1.x; a0.y += a1.y; a0.z += a1.z; a0.w += a1.w;

    // Fold the two row-groups within each warp (lane ^ 16 has same colg).
    a0.x += __shfl_xor_sync(0xFFFFFFFFu, a0.x, 16);
    a0.y += __shfl_xor_sync(0xFFFFFFFFu, a0.y, 16);
    a0.z += __shfl_xor_sync(0xFFFFFFFFu, a0.z, 16);
    a0.w += __shfl_xor_sync(0xFFFFFFFFu, a0.w, 16);

    #pragma unroll
    for (int m = 16; m >= 1; m >>= 1) {
        ksq += __shfl_xor_sync(0xFFFFFFFFu, ksq, m);
        qsq += __shfl_xor_sync(0xFFFFFFFFu, qsq, m);
    }

    __shared__ float4 s_acc[8][16];
    __shared__ float  s_ksq[8];
    __shared__ float  s_qsq[8];
    const int warp = t >> 5;
    const int lane = t & 31;
    if (lane < 16) s_acc[warp][lane] = a0;
    if (lane == 0) { s_ksq[warp] = ksq; s_qsq[warp] = qsq; }
    __syncthreads();

    float* __restrict__ outp = g_part + (size_t)(bh * NSPLIT + split) * PSTRIDE;
    if (t < 16) {
        float4 a = s_acc[0][t];
        #pragma unroll
        for (int w = 1; w < 8; ++w) {
            float4 b = s_acc[w][t];
            a.x += b.x; a.y += b.y; a.z += b.z; a.w += b.w;
        }
        reinterpret_cast<float4*>(outp)[t] = a;
    } else if (t == 16) {
        float a = 0.f, b = 0.f;
        #pragma unroll
        for (int w = 0; w < 8; ++w) { a += s_ksq[w]; b += s_qsq[w]; }
        outp[64] = a;
        outp[65] = b;
    }
}

// ---------------------------------------------------------------------------
// Kernel 2 (fused combine + broadcast): unchanged from R3 (41.8us @ ~6.2TB/s).
// ---------------------------------------------------------------------------
#define BROWS 256
__global__ __launch_bounds__(256) void broadcast_kernel(
    const float* __restrict__ Q,
    float* __restrict__ out)
{
    const size_t row0 = (size_t)blockIdx.x * BROWS;  // 256 | 16384 -> single bh
    const int    t    = threadIdx.x;
    const int    bh   = (int)(row0 >> 14);

    __shared__ float s_coef[DV];
    __shared__ float s_scale;
    __shared__ float sQ[BROWS];

    sQ[t] = Q[row0 + t];

    const float* __restrict__ base = g_part + (size_t)bh * NSPLIT * PSTRIDE;
    if (t < DV) {
        float ktv = 0.f;
        #pragma unroll
        for (int s = 0; s < NSPLIT; ++s) ktv += base[(size_t)s * PSTRIDE + t];
        s_coef[t] = ktv;
    } else if (t == DV) {
        float ksq = 0.f, qsq = 0.f;
        #pragma unroll
        for (int s = 0; s < NSPLIT; ++s) {
            ksq += base[(size_t)s * PSTRIDE + 64];
            qsq += base[(size_t)s * PSTRIDE + 65];
        }
        s_scale = 1.0f / (sqrtf(ksq) * sqrtf(qsq));
    }
    __syncthreads();

    const int rg = t >> 4;
    const int cg = t & 15;
    const float scale = s_scale;
    float4 c = reinterpret_cast<const float4*>(s_coef)[cg];
    c.x *= scale; c.y *= scale; c.z *= scale; c.w *= scale;

    #pragma unroll
    for (int ri = 0; ri < BROWS / 16; ++ri) {
        const int    lr  = ri * 16 + rg;
        const size_t row = row0 + lr;
        const float  q   = sQ[lr];
        float4 o;
        o.x = q * c.x;
        o.y = q * c.y;
        o.z = q * c.z;
        o.w = q * c.w;
        __stcs(reinterpret_cast<float4*>(out) + row * 16 + cg, o);
    }
}

// ---------------------------------------------------------------------------
extern "C" void kernel_launch(void* const* d_in, const int* in_sizes, int n_in,
                              void* d_out, int out_size)
{
    const float* Q = (const float*)d_in[0];
    const float* K = (const float*)d_in[1];
    const float* V = (const float*)d_in[2];
    float* out = (float*)d_out;

    reduce_kernel<<<BH * NSPLIT, 256>>>(Q, K, V);
    broadcast_kernel<<<(BH * SEQ) / BROWS, 256>>>(Q, out);
}